// round 2
// baseline (speedup 1.0000x reference)
#include <cuda_runtime.h>
#include <math.h>

// FluxRoPEAttention: B=1, H=24, L=4096, D=128, fp32.
// out[l, h*128+d] = softmax(rope(q) @ rope(k)^T / sqrt(128)) @ v
//
// SIMT fp32 flash-attention baseline using packed fma.rn.f32x2 (Blackwell).

namespace {

constexpr int H  = 24;
constexpr int L  = 4096;
constexpr int D  = 128;
constexpr int BM = 64;
constexpr int BN = 64;
constexpr int QP = 132;   // Q smem pitch (floats)
constexpr int KP = 132;   // K smem pitch
constexpr int VP = 128;   // V smem pitch
constexpr int PP = 68;    // P smem pitch
constexpr int NTHREADS = 256;
constexpr int SMEM_BYTES = (BM * QP + BN * KP + BN * VP + BM * PP) * 4; // 117760

typedef unsigned long long u64;

__device__ __forceinline__ u64 ffma2(u64 a, u64 b, u64 c) {
    u64 d;
    asm("fma.rn.f32x2 %0, %1, %2, %3;" : "=l"(d) : "l"(a), "l"(b), "l"(c));
    return d;
}
__device__ __forceinline__ u64 fmul2(u64 a, u64 b) {
    u64 d;
    asm("mul.rn.f32x2 %0, %1, %2;" : "=l"(d) : "l"(a), "l"(b));
    return d;
}
__device__ __forceinline__ u64 pack2(float lo, float hi) {
    u64 r;
    asm("mov.b64 %0, {%1, %2};" : "=l"(r) : "f"(lo), "f"(hi));
    return r;
}
__device__ __forceinline__ void unpack2(u64 v, float& lo, float& hi) {
    asm("mov.b64 {%0, %1}, %2;" : "=f"(lo), "=f"(hi) : "l"(v));
}

__global__ void __launch_bounds__(NTHREADS)
fa_rope_kernel(const float* __restrict__ q, const float* __restrict__ k,
               const float* __restrict__ v, const float* __restrict__ pe,
               float* __restrict__ out)
{
    extern __shared__ float smem[];
    float* Qs = smem;                 // [BM][QP]
    float* Ks = Qs + BM * QP;         // [BN][KP]
    float* Vs = Ks + BN * KP;         // [BN][VP]
    float* Ps = Vs + BN * VP;         // [BM][PP]

    const int h   = blockIdx.y;
    const int q0  = blockIdx.x * BM;
    const int tid = threadIdx.x;
    const int ty  = tid >> 4;   // 0..15  -> owns S rows 4*ty..4*ty+3
    const int tx  = tid & 15;   // 0..15  -> owns S cols {16j+tx}, O cols {64cc+4tx..+3}

    const float scale = 0.08838834764831845f; // 1/sqrt(128)

    // ---- Load Q tile with RoPE, pre-scaled ----
    {
        const float* qb = q + ((size_t)h * L + q0) * D;
        #pragma unroll
        for (int it = 0; it < (BM * (D / 2)) / NTHREADS; it++) {
            int idx = it * NTHREADS + tid;
            int row = idx >> 6;      // 64 pairs per row
            int i   = idx & 63;
            float2 qq = *(const float2*)(qb + row * D + 2 * i);
            float2 cs = *(const float2*)(pe + ((size_t)(q0 + row) * 64 + i) * 2);
            float re = qq.x * cs.x - qq.y * cs.y;
            float im = qq.x * cs.y + qq.y * cs.x;
            *(float2*)(Qs + row * QP + 2 * i) = make_float2(re * scale, im * scale);
        }
    }

    // ---- Accumulators (persist across KV loop) ----
    u64 o2[4][4];           // [row i][pair c]: d = 64*(c>>1) + 4*tx + 2*(c&1)
    #pragma unroll
    for (int i = 0; i < 4; i++)
        #pragma unroll
        for (int c = 0; c < 4; c++) o2[i][c] = 0ull;   // bits 0 == {0.f,0.f}
    float m_i[4], l_i[4];
    #pragma unroll
    for (int i = 0; i < 4; i++) { m_i[i] = -INFINITY; l_i[i] = 0.f; }

    for (int kt = 0; kt < L; kt += BN) {
        __syncthreads();   // prior PV done; safe to overwrite K/V/P (also covers Q on iter 0)

        // ---- Load K tile with RoPE ----
        {
            const float* kb = k + ((size_t)h * L + kt) * D;
            #pragma unroll
            for (int it = 0; it < (BN * (D / 2)) / NTHREADS; it++) {
                int idx = it * NTHREADS + tid;
                int row = idx >> 6;
                int i   = idx & 63;
                float2 kk2 = *(const float2*)(kb + row * D + 2 * i);
                float2 cs  = *(const float2*)(pe + ((size_t)(kt + row) * 64 + i) * 2);
                float re = kk2.x * cs.x - kk2.y * cs.y;
                float im = kk2.x * cs.y + kk2.y * cs.x;
                *(float2*)(Ks + row * KP + 2 * i) = make_float2(re, im);
            }
        }
        // ---- Load V tile ----
        {
            const float* vb = v + ((size_t)h * L + kt) * D;
            #pragma unroll
            for (int it = 0; it < (BN * D / 4) / NTHREADS; it++) {
                int idx  = it * NTHREADS + tid;
                int row  = idx >> 5;          // 32 float4 per row
                int col4 = (idx & 31) * 4;
                *(float4*)(Vs + row * VP + col4) = *(const float4*)(vb + row * D + col4);
            }
        }
        __syncthreads();

        // ---- S = Qs @ Ks^T  (f32x2 packed over k: two partial sums per element) ----
        u64 acc[4][4];
        #pragma unroll
        for (int i = 0; i < 4; i++)
            #pragma unroll
            for (int j = 0; j < 4; j++) acc[i][j] = 0ull;

        const ulonglong2* qp[4];
        const ulonglong2* kp[4];
        #pragma unroll
        for (int i = 0; i < 4; i++) qp[i] = (const ulonglong2*)(Qs + (4 * ty + i) * QP);
        #pragma unroll
        for (int j = 0; j < 4; j++) kp[j] = (const ulonglong2*)(Ks + (16 * j + tx) * KP);

        #pragma unroll 2
        for (int kk = 0; kk < D / 4; kk++) {     // 4 k-values per step
            ulonglong2 a[4], b[4];
            #pragma unroll
            for (int i = 0; i < 4; i++) a[i] = qp[i][kk];
            #pragma unroll
            for (int j = 0; j < 4; j++) b[j] = kp[j][kk];
            #pragma unroll
            for (int i = 0; i < 4; i++)
                #pragma unroll
                for (int j = 0; j < 4; j++) {
                    acc[i][j] = ffma2(a[i].x, b[j].x, acc[i][j]);
                    acc[i][j] = ffma2(a[i].y, b[j].y, acc[i][j]);
                }
        }

        // ---- Online softmax (row groups = 16 lanes sharing ty; shfl stays in half-warp) ----
        float s[4][4];
        #pragma unroll
        for (int i = 0; i < 4; i++)
            #pragma unroll
            for (int j = 0; j < 4; j++) {
                float lo, hi;
                unpack2(acc[i][j], lo, hi);
                s[i][j] = lo + hi;
            }

        #pragma unroll
        for (int i = 0; i < 4; i++) {
            float tmax = fmaxf(fmaxf(s[i][0], s[i][1]), fmaxf(s[i][2], s[i][3]));
            #pragma unroll
            for (int off = 8; off; off >>= 1)
                tmax = fmaxf(tmax, __shfl_xor_sync(0xffffffffu, tmax, off));
            float mnew  = fmaxf(m_i[i], tmax);
            float alpha = __expf(m_i[i] - mnew);
            m_i[i] = mnew;

            float p[4];
            float rs = 0.f;
            #pragma unroll
            for (int j = 0; j < 4; j++) { p[j] = __expf(s[i][j] - mnew); rs += p[j]; }
            #pragma unroll
            for (int off = 8; off; off >>= 1)
                rs += __shfl_xor_sync(0xffffffffu, rs, off);
            l_i[i] = l_i[i] * alpha + rs;

            u64 a2 = pack2(alpha, alpha);
            #pragma unroll
            for (int c = 0; c < 4; c++) o2[i][c] = fmul2(o2[i][c], a2);

            #pragma unroll
            for (int j = 0; j < 4; j++)
                Ps[(4 * ty + i) * PP + 16 * j + tx] = p[j];
        }
        __syncthreads();

        // ---- O += P @ V  (f32x2 packed over d; P read as float4, broadcast) ----
        {
            const float* pr[4];
            #pragma unroll
            for (int i = 0; i < 4; i++) pr[i] = Ps + (4 * ty + i) * PP;
            const float* vb0 = Vs + tx * 4;

            #pragma unroll 2
            for (int ss = 0; ss < BN; ss += 4) {
                float4 p4[4];
                #pragma unroll
                for (int i = 0; i < 4; i++) p4[i] = *(const float4*)(pr[i] + ss);

                #pragma unroll
                for (int u = 0; u < 4; u++) {
                    ulonglong2 va = *(const ulonglong2*)(vb0 + (ss + u) * VP);
                    ulonglong2 vc = *(const ulonglong2*)(vb0 + (ss + u) * VP + 64);
                    u64 vv[4] = { va.x, va.y, vc.x, vc.y };
                    #pragma unroll
                    for (int i = 0; i < 4; i++) {
                        float pv = (u == 0) ? p4[i].x : (u == 1) ? p4[i].y
                                 : (u == 2) ? p4[i].z : p4[i].w;
                        u64 p2 = pack2(pv, pv);
                        #pragma unroll
                        for (int c = 0; c < 4; c++)
                            o2[i][c] = ffma2(p2, vv[c], o2[i][c]);
                    }
                }
            }
        }
    }

    // ---- Epilogue: normalize and write out[l, h*128 + d] ----
    #pragma unroll
    for (int i = 0; i < 4; i++) {
        float inv = 1.0f / l_i[i];
        int row = q0 + 4 * ty + i;
        float* ob = out + (size_t)row * (H * D) + h * D;
        #pragma unroll
        for (int cc = 0; cc < 2; cc++) {
            float x0, x1, x2, x3;
            unpack2(o2[i][2 * cc],     x0, x1);
            unpack2(o2[i][2 * cc + 1], x2, x3);
            *(float4*)(ob + cc * 64 + tx * 4) =
                make_float4(x0 * inv, x1 * inv, x2 * inv, x3 * inv);
        }
    }
}

} // namespace

extern "C" void kernel_launch(void* const* d_in, const int* in_sizes, int n_in,
                              void* d_out, int out_size)
{
    const float* q  = (const float*)d_in[0];
    const float* k  = (const float*)d_in[1];
    const float* v  = (const float*)d_in[2];
    const float* pe = (const float*)d_in[3];
    float* out = (float*)d_out;

    cudaFuncSetAttribute(fa_rope_kernel,
                         cudaFuncAttributeMaxDynamicSharedMemorySize, SMEM_BYTES);

    dim3 grid(L / BM, H);
    fa_rope_kernel<<<grid, NTHREADS, SMEM_BYTES>>>(q, k, v, pe, out);
}

// round 4
// speedup vs baseline: 3.8367x; 3.8367x over previous
#include <cuda_runtime.h>
#include <cuda_fp16.h>
#include <math.h>
#include <stdint.h>

// FluxRoPEAttention fp16 tensor-core flash attention.
// Pre-pass: RoPE(Q)*scale, RoPE(K), V -> fp16 scratch.
// Main: FA2-style mma.sync.m16n8k16, fp32 accum, online softmax.

namespace {

constexpr int H = 24, L = 4096, D = 128;
constexpr int BM = 64, BN = 64;
constexpr int NTH = 128;             // 4 warps
constexpr int PIT = 136;             // smem pitch in halves (272 B rows)
constexpr int TSZ = BM * PIT;        // halves per tile buffer (8704)
constexpr int SMEM_BYTES = 5 * TSZ * 2;   // Q + 2xK + 2xV = 87040 B
constexpr int NT = L / BN;           // 64 KV tiles

__device__ __half g_Qh[(size_t)H * L * D];
__device__ __half g_Kh[(size_t)H * L * D];
__device__ __half g_Vh[(size_t)H * L * D];

// ---------------- pre-pass ----------------
__global__ void prep_kernel(const float* __restrict__ q, const float* __restrict__ k,
                            const float* __restrict__ v, const float* __restrict__ pe)
{
    const int job = blockIdx.y;
    size_t idx = (size_t)blockIdx.x * blockDim.x + threadIdx.x;   // over H*L*64
    size_t h   = idx >> 18;          // / (4096*64)
    size_t rem = idx & 262143;
    size_t l   = rem >> 6;
    size_t i   = rem & 63;
    size_t off = (h * L + l) * D + 2 * i;

    if (job == 0) {
        float2 x  = *(const float2*)(q + off);
        float2 cs = *(const float2*)(pe + (l * 64 + i) * 2);
        const float s = 0.08838834764831845f;
        float re = (x.x * cs.x - x.y * cs.y) * s;
        float im = (x.x * cs.y + x.y * cs.x) * s;
        *(__half2*)(g_Qh + off) = __floats2half2_rn(re, im);
    } else if (job == 1) {
        float2 x  = *(const float2*)(k + off);
        float2 cs = *(const float2*)(pe + (l * 64 + i) * 2);
        float re = x.x * cs.x - x.y * cs.y;
        float im = x.x * cs.y + x.y * cs.x;
        *(__half2*)(g_Kh + off) = __floats2half2_rn(re, im);
    } else {
        float2 x = *(const float2*)(v + off);
        *(__half2*)(g_Vh + off) = __floats2half2_rn(x.x, x.y);
    }
}

// ---------------- PTX helpers ----------------
__device__ __forceinline__ void ldsm4(uint32_t& r0, uint32_t& r1, uint32_t& r2, uint32_t& r3, uint32_t a) {
    asm volatile("ldmatrix.sync.aligned.m8n8.x4.shared.b16 {%0,%1,%2,%3}, [%4];"
                 : "=r"(r0), "=r"(r1), "=r"(r2), "=r"(r3) : "r"(a));
}
__device__ __forceinline__ void ldsm4t(uint32_t& r0, uint32_t& r1, uint32_t& r2, uint32_t& r3, uint32_t a) {
    asm volatile("ldmatrix.sync.aligned.m8n8.x4.trans.shared.b16 {%0,%1,%2,%3}, [%4];"
                 : "=r"(r0), "=r"(r1), "=r"(r2), "=r"(r3) : "r"(a));
}
__device__ __forceinline__ void mma16816(float* c, uint32_t a0, uint32_t a1, uint32_t a2, uint32_t a3,
                                         uint32_t b0, uint32_t b1) {
    asm volatile("mma.sync.aligned.m16n8k16.row.col.f32.f16.f16.f32 "
                 "{%0,%1,%2,%3}, {%4,%5,%6,%7}, {%8,%9}, {%0,%1,%2,%3};"
                 : "+f"(c[0]), "+f"(c[1]), "+f"(c[2]), "+f"(c[3])
                 : "r"(a0), "r"(a1), "r"(a2), "r"(a3), "r"(b0), "r"(b1));
}
__device__ __forceinline__ uint32_t pk2h(float lo, float hi) {
    uint32_t u;
    asm("cvt.rn.f16x2.f32 %0, %1, %2;" : "=r"(u) : "f"(hi), "f"(lo));
    return u;
}
__device__ __forceinline__ void cpa16(uint32_t dst, const void* src) {
    asm volatile("cp.async.ca.shared.global [%0], [%1], 16;" :: "r"(dst), "l"(src));
}

// ---------------- main kernel ----------------
__global__ void __launch_bounds__(NTH)
fa16_kernel(float* __restrict__ out)
{
    extern __shared__ __half sm[];
    const uint32_t sbase = (uint32_t)__cvta_generic_to_shared(sm);
    const int h    = blockIdx.y;
    const int q0   = blockIdx.x * BM;
    const int tid  = threadIdx.x;
    const int w    = tid >> 5;
    const int lane = tid & 31;

    const __half* Qg = g_Qh + ((size_t)h * L + q0) * D;
    const __half* Kg = g_Kh + (size_t)h * L * D;
    const __half* Vg = g_Vh + (size_t)h * L * D;

    // smem half-offsets: Q at 0, K buffers at TSZ*(1+b), V buffers at TSZ*(3+b)
    auto load_tile = [&](uint32_t dst_halves, const __half* src) {
        int row = tid >> 1;
        int hc  = (tid & 1) * 64;
        const __half* sp = src + row * D + hc;
        uint32_t dp = sbase + (dst_halves + row * PIT + hc) * 2;
        #pragma unroll
        for (int c = 0; c < 8; c++)
            cpa16(dp + c * 16, sp + c * 8);
    };

    load_tile(0,       Qg);
    load_tile(TSZ,     Kg);
    load_tile(3 * TSZ, Vg);
    asm volatile("cp.async.commit_group;");

    float o[16][4];
    #pragma unroll
    for (int j = 0; j < 16; j++)
        #pragma unroll
        for (int x = 0; x < 4; x++) o[j][x] = 0.f;
    float m0 = -INFINITY, m1 = -INFINITY, l0 = 0.f, l1 = 0.f;

    // ldmatrix lane-address bases (in halves)
    const uint32_t a_off = (16 * w + (lane & 15)) * PIT + ((lane >> 4) << 3);
    const uint32_t b_off = ((lane & 7) + ((lane >> 4) << 3)) * PIT + (((lane >> 3) & 1) << 3);
    const uint32_t v_off = ((lane & 7) + (((lane >> 3) & 1) << 3)) * PIT + ((lane >> 4) << 3);

    for (int t = 0; t < NT; t++) {
        asm volatile("cp.async.wait_group 0;");
        __syncthreads();
        if (t + 1 < NT) {
            int nb = (t + 1) & 1;
            load_tile(TSZ * (1 + nb), Kg + (size_t)(t + 1) * BN * D);
            load_tile(TSZ * (3 + nb), Vg + (size_t)(t + 1) * BN * D);
            asm volatile("cp.async.commit_group;");
        }
        const int b = t & 1;
        const uint32_t QB = sbase;
        const uint32_t KB = sbase + TSZ * (1 + b) * 2;
        const uint32_t VB = sbase + TSZ * (3 + b) * 2;

        // ---- S = Q K^T ----
        float c[8][4];
        #pragma unroll
        for (int j = 0; j < 8; j++) { c[j][0] = c[j][1] = c[j][2] = c[j][3] = 0.f; }

        #pragma unroll
        for (int kc = 0; kc < 8; kc++) {
            uint32_t a0, a1, a2, a3;
            ldsm4(a0, a1, a2, a3, QB + (a_off + kc * 16) * 2);
            #pragma unroll
            for (int np = 0; np < 4; np++) {
                uint32_t b0, b1, b2, b3;
                ldsm4(b0, b1, b2, b3, KB + (b_off + np * 16 * PIT + kc * 16) * 2);
                mma16816(c[2 * np],     a0, a1, a2, a3, b0, b1);
                mma16816(c[2 * np + 1], a0, a1, a2, a3, b2, b3);
            }
        }

        // ---- online softmax (rows lane>>2 and +8) ----
        float rmax0 = -INFINITY, rmax1 = -INFINITY;
        #pragma unroll
        for (int j = 0; j < 8; j++) {
            rmax0 = fmaxf(rmax0, fmaxf(c[j][0], c[j][1]));
            rmax1 = fmaxf(rmax1, fmaxf(c[j][2], c[j][3]));
        }
        #pragma unroll
        for (int off = 1; off <= 2; off <<= 1) {
            rmax0 = fmaxf(rmax0, __shfl_xor_sync(0xffffffffu, rmax0, off));
            rmax1 = fmaxf(rmax1, __shfl_xor_sync(0xffffffffu, rmax1, off));
        }
        float mn0 = fmaxf(m0, rmax0), mn1 = fmaxf(m1, rmax1);
        float al0 = __expf(m0 - mn0), al1 = __expf(m1 - mn1);
        m0 = mn0; m1 = mn1;

        float rs0 = 0.f, rs1 = 0.f;
        #pragma unroll
        for (int j = 0; j < 8; j++) {
            c[j][0] = __expf(c[j][0] - mn0); c[j][1] = __expf(c[j][1] - mn0);
            c[j][2] = __expf(c[j][2] - mn1); c[j][3] = __expf(c[j][3] - mn1);
            rs0 += c[j][0] + c[j][1];
            rs1 += c[j][2] + c[j][3];
        }
        #pragma unroll
        for (int off = 1; off <= 2; off <<= 1) {
            rs0 += __shfl_xor_sync(0xffffffffu, rs0, off);
            rs1 += __shfl_xor_sync(0xffffffffu, rs1, off);
        }
        l0 = l0 * al0 + rs0;
        l1 = l1 * al1 + rs1;

        #pragma unroll
        for (int j = 0; j < 16; j++) {
            o[j][0] *= al0; o[j][1] *= al0;
            o[j][2] *= al1; o[j][3] *= al1;
        }

        // pack P into A-operand fragments (register reuse, no smem round-trip)
        uint32_t pA[8], pB[8];
        #pragma unroll
        for (int j = 0; j < 8; j++) {
            pA[j] = pk2h(c[j][0], c[j][1]);
            pB[j] = pk2h(c[j][2], c[j][3]);
        }

        // ---- O += P V ----
        #pragma unroll
        for (int kc = 0; kc < 4; kc++) {
            #pragma unroll
            for (int dp = 0; dp < 8; dp++) {
                uint32_t b0, b1, b2, b3;
                ldsm4t(b0, b1, b2, b3, VB + (v_off + kc * 16 * PIT + dp * 16) * 2);
                mma16816(o[2 * dp],     pA[2 * kc], pB[2 * kc], pA[2 * kc + 1], pB[2 * kc + 1], b0, b1);
                mma16816(o[2 * dp + 1], pA[2 * kc], pB[2 * kc], pA[2 * kc + 1], pB[2 * kc + 1], b2, b3);
            }
        }
    }

    // ---- epilogue: normalize, write out[l, h*128 + d] ----
    float inv0 = 1.f / l0, inv1 = 1.f / l1;
    int r0 = q0 + 16 * w + (lane >> 2);
    float* ob0 = out + (size_t)r0 * (H * D) + h * D + 2 * (lane & 3);
    float* ob1 = ob0 + (size_t)8 * (H * D);
    #pragma unroll
    for (int j = 0; j < 16; j++) {
        *(float2*)(ob0 + 8 * j) = make_float2(o[j][0] * inv0, o[j][1] * inv0);
        *(float2*)(ob1 + 8 * j) = make_float2(o[j][2] * inv1, o[j][3] * inv1);
    }
}

} // namespace

extern "C" void kernel_launch(void* const* d_in, const int* in_sizes, int n_in,
                              void* d_out, int out_size)
{
    const float* q  = (const float*)d_in[0];
    const float* k  = (const float*)d_in[1];
    const float* v  = (const float*)d_in[2];
    const float* pe = (const float*)d_in[3];
    float* out = (float*)d_out;

    prep_kernel<<<dim3((H * L * 64) / 256, 3), 256>>>(q, k, v, pe);

    cudaFuncSetAttribute(fa16_kernel,
                         cudaFuncAttributeMaxDynamicSharedMemorySize, SMEM_BYTES);
    fa16_kernel<<<dim3(L / BM, H), NTH, SMEM_BYTES>>>(out);
}

// round 10
// speedup vs baseline: 6.0491x; 1.5766x over previous
#include <cuda_runtime.h>
#include <cuda_fp16.h>
#include <math.h>
#include <stdint.h>

// FluxRoPEAttention fp16 tensor-core flash attention (sm_100 baseline ISA).
// Pre-pass: RoPE(Q)*scale, RoPE(K), V -> fp16 scratch.
// Main: FA2-style mma.sync.m16n8k16, fp32 accum, online softmax.
// R8: BM=128 with 8 warps/CTA (same per-warp tile) -> 16 warps/SM.

namespace {

constexpr int H = 24, L = 4096, D = 128;
constexpr int BM = 128, BN = 64;
constexpr int NTH = 256;             // 8 warps
constexpr int PIT = 136;             // smem pitch in halves (272 B rows)
constexpr int QSZ = BM * PIT;        // 17408 halves
constexpr int KSZ = BN * PIT;        // 8704 halves per K/V buffer
constexpr int SMEM_BYTES = (QSZ + 4 * KSZ) * 2;   // 104448 B
constexpr int NT = L / BN;           // 64 KV tiles

__device__ __half g_Qh[(size_t)H * L * D];
__device__ __half g_Kh[(size_t)H * L * D];
__device__ __half g_Vh[(size_t)H * L * D];

// ---------------- pre-pass ----------------
__global__ void prep_kernel(const float* __restrict__ q, const float* __restrict__ k,
                            const float* __restrict__ v, const float* __restrict__ pe)
{
    const int job = blockIdx.y;
    size_t idx = (size_t)blockIdx.x * blockDim.x + threadIdx.x;   // over H*L*64
    size_t h   = idx >> 18;
    size_t rem = idx & 262143;
    size_t l   = rem >> 6;
    size_t i   = rem & 63;
    size_t off = (h * L + l) * D + 2 * i;

    if (job == 0) {
        float2 x  = *(const float2*)(q + off);
        float2 cs = *(const float2*)(pe + (l * 64 + i) * 2);
        const float s = 0.08838834764831845f;
        float re = (x.x * cs.x - x.y * cs.y) * s;
        float im = (x.x * cs.y + x.y * cs.x) * s;
        *(__half2*)(g_Qh + off) = __floats2half2_rn(re, im);
    } else if (job == 1) {
        float2 x  = *(const float2*)(k + off);
        float2 cs = *(const float2*)(pe + (l * 64 + i) * 2);
        float re = x.x * cs.x - x.y * cs.y;
        float im = x.x * cs.y + x.y * cs.x;
        *(__half2*)(g_Kh + off) = __floats2half2_rn(re, im);
    } else {
        float2 x = *(const float2*)(v + off);
        *(__half2*)(g_Vh + off) = __floats2half2_rn(x.x, x.y);
    }
}

// ---------------- PTX helpers ----------------
__device__ __forceinline__ void ldsm4(uint32_t& r0, uint32_t& r1, uint32_t& r2, uint32_t& r3, uint32_t a) {
    asm volatile("ldmatrix.sync.aligned.m8n8.x4.shared.b16 {%0,%1,%2,%3}, [%4];"
                 : "=r"(r0), "=r"(r1), "=r"(r2), "=r"(r3) : "r"(a));
}
__device__ __forceinline__ void ldsm4t(uint32_t& r0, uint32_t& r1, uint32_t& r2, uint32_t& r3, uint32_t a) {
    asm volatile("ldmatrix.sync.aligned.m8n8.x4.trans.shared.b16 {%0,%1,%2,%3}, [%4];"
                 : "=r"(r0), "=r"(r1), "=r"(r2), "=r"(r3) : "r"(a));
}
__device__ __forceinline__ void mma16816(float* c, uint32_t a0, uint32_t a1, uint32_t a2, uint32_t a3,
                                         uint32_t b0, uint32_t b1) {
    asm volatile("mma.sync.aligned.m16n8k16.row.col.f32.f16.f16.f32 "
                 "{%0,%1,%2,%3}, {%4,%5,%6,%7}, {%8,%9}, {%0,%1,%2,%3};"
                 : "+f"(c[0]), "+f"(c[1]), "+f"(c[2]), "+f"(c[3])
                 : "r"(a0), "r"(a1), "r"(a2), "r"(a3), "r"(b0), "r"(b1));
}
__device__ __forceinline__ uint32_t pk2h(float lo, float hi) {
    uint32_t u;
    asm("cvt.rn.f16x2.f32 %0, %1, %2;" : "=r"(u) : "f"(hi), "f"(lo));
    return u;
}
__device__ __forceinline__ void cpa16(uint32_t dst, const void* src) {
    asm volatile("cp.async.ca.shared.global [%0], [%1], 16;" :: "r"(dst), "l"(src));
}

// ---------------- main kernel ----------------
__global__ void __launch_bounds__(NTH, 2)
fa16_kernel(float* __restrict__ out)
{
    extern __shared__ __half sm[];
    const uint32_t sbase = (uint32_t)__cvta_generic_to_shared(sm);
    const int h    = blockIdx.y;
    const int q0   = blockIdx.x * BM;
    const int tid  = threadIdx.x;
    const int w    = tid >> 5;
    const int lane = tid & 31;

    const __half* Qg = g_Qh + ((size_t)h * L + q0) * D;
    const __half* Kg = g_Kh + (size_t)h * L * D;
    const __half* Vg = g_Vh + (size_t)h * L * D;

    // Q: 128 rows; 256 threads -> 2 threads/row, 8 cpa each
    {
        int row = tid >> 1;
        int hc  = (tid & 1) * 64;
        const __half* sp = Qg + row * D + hc;
        uint32_t dp = sbase + (row * PIT + hc) * 2;
        #pragma unroll
        for (int c = 0; c < 8; c++) cpa16(dp + c * 16, sp + c * 8);
    }
    // K/V: 64 rows; 256 threads -> 4 threads/row, 4 cpa each
    auto load_kv = [&](uint32_t dst_halves, const __half* src) {
        int row = tid >> 2;
        int hc  = (tid & 3) * 32;
        const __half* sp = src + row * D + hc;
        uint32_t dp = sbase + (dst_halves + row * PIT + hc) * 2;
        #pragma unroll
        for (int c = 0; c < 4; c++) cpa16(dp + c * 16, sp + c * 8);
    };

    load_kv(QSZ,           Kg);
    load_kv(QSZ + 2 * KSZ, Vg);
    asm volatile("cp.async.commit_group;");

    float o[16][4];
    #pragma unroll
    for (int j = 0; j < 16; j++)
        #pragma unroll
        for (int x = 0; x < 4; x++) o[j][x] = 0.f;
    float m0 = -INFINITY, m1 = -INFINITY, l0 = 0.f, l1 = 0.f;

    // ldmatrix lane-address bases (in halves)
    const uint32_t a_off = (16 * w + (lane & 15)) * PIT + ((lane >> 4) << 3);
    const uint32_t b_off = ((lane & 7) + ((lane >> 4) << 3)) * PIT + (((lane >> 3) & 1) << 3);
    const uint32_t v_off = ((lane & 7) + (((lane >> 3) & 1) << 3)) * PIT + ((lane >> 4) << 3);

    for (int t = 0; t < NT; t++) {
        asm volatile("cp.async.wait_group 0;");
        __syncthreads();
        if (t + 1 < NT) {
            int nb = (t + 1) & 1;
            load_kv(QSZ + nb * KSZ,       Kg + (size_t)(t + 1) * BN * D);
            load_kv(QSZ + (2 + nb) * KSZ, Vg + (size_t)(t + 1) * BN * D);
            asm volatile("cp.async.commit_group;");
        }
        const int b = t & 1;
        const uint32_t QB = sbase;
        const uint32_t KB = sbase + (QSZ + b * KSZ) * 2;
        const uint32_t VB = sbase + (QSZ + (2 + b) * KSZ) * 2;

        // ---- S = Q K^T ----
        float c[8][4];
        #pragma unroll
        for (int j = 0; j < 8; j++) { c[j][0] = c[j][1] = c[j][2] = c[j][3] = 0.f; }

        #pragma unroll
        for (int kc = 0; kc < 8; kc++) {
            uint32_t a0, a1, a2, a3;
            ldsm4(a0, a1, a2, a3, QB + (a_off + kc * 16) * 2);
            #pragma unroll
            for (int np = 0; np < 4; np++) {
                uint32_t b0, b1, b2, b3;
                ldsm4(b0, b1, b2, b3, KB + (b_off + np * 16 * PIT + kc * 16) * 2);
                mma16816(c[2 * np],     a0, a1, a2, a3, b0, b1);
                mma16816(c[2 * np + 1], a0, a1, a2, a3, b2, b3);
            }
        }

        // ---- online softmax (rows lane>>2 and +8) ----
        float rmax0 = -INFINITY, rmax1 = -INFINITY;
        #pragma unroll
        for (int j = 0; j < 8; j++) {
            rmax0 = fmaxf(rmax0, fmaxf(c[j][0], c[j][1]));
            rmax1 = fmaxf(rmax1, fmaxf(c[j][2], c[j][3]));
        }
        #pragma unroll
        for (int off = 1; off <= 2; off <<= 1) {
            rmax0 = fmaxf(rmax0, __shfl_xor_sync(0xffffffffu, rmax0, off));
            rmax1 = fmaxf(rmax1, __shfl_xor_sync(0xffffffffu, rmax1, off));
        }
        float mn0 = fmaxf(m0, rmax0), mn1 = fmaxf(m1, rmax1);
        float al0 = __expf(m0 - mn0), al1 = __expf(m1 - mn1);
        m0 = mn0; m1 = mn1;

        float rs0 = 0.f, rs1 = 0.f;
        #pragma unroll
        for (int j = 0; j < 8; j++) {
            c[j][0] = __expf(c[j][0] - mn0); c[j][1] = __expf(c[j][1] - mn0);
            c[j][2] = __expf(c[j][2] - mn1); c[j][3] = __expf(c[j][3] - mn1);
            rs0 += c[j][0] + c[j][1];
            rs1 += c[j][2] + c[j][3];
        }
        #pragma unroll
        for (int off = 1; off <= 2; off <<= 1) {
            rs0 += __shfl_xor_sync(0xffffffffu, rs0, off);
            rs1 += __shfl_xor_sync(0xffffffffu, rs1, off);
        }
        l0 = l0 * al0 + rs0;
        l1 = l1 * al1 + rs1;

        #pragma unroll
        for (int j = 0; j < 16; j++) {
            o[j][0] *= al0; o[j][1] *= al0;
            o[j][2] *= al1; o[j][3] *= al1;
        }

        // pack P into A-operand fragments (register reuse, no smem round-trip)
        uint32_t pA[8], pB[8];
        #pragma unroll
        for (int j = 0; j < 8; j++) {
            pA[j] = pk2h(c[j][0], c[j][1]);
            pB[j] = pk2h(c[j][2], c[j][3]);
        }

        // ---- O += P V ----
        #pragma unroll
        for (int kc = 0; kc < 4; kc++) {
            #pragma unroll
            for (int dp = 0; dp < 8; dp++) {
                uint32_t b0, b1, b2, b3;
                ldsm4t(b0, b1, b2, b3, VB + (v_off + kc * 16 * PIT + dp * 16) * 2);
                mma16816(o[2 * dp],     pA[2 * kc], pB[2 * kc], pA[2 * kc + 1], pB[2 * kc + 1], b0, b1);
                mma16816(o[2 * dp + 1], pA[2 * kc], pB[2 * kc], pA[2 * kc + 1], pB[2 * kc + 1], b2, b3);
            }
        }
    }

    // ---- epilogue: normalize, write out[l, h*128 + d] ----
    float inv0 = 1.f / l0, inv1 = 1.f / l1;
    int r0 = q0 + 16 * w + (lane >> 2);
    float* ob0 = out + (size_t)r0 * (H * D) + h * D + 2 * (lane & 3);
    float* ob1 = ob0 + (size_t)8 * (H * D);
    #pragma unroll
    for (int j = 0; j < 16; j++) {
        *(float2*)(ob0 + 8 * j) = make_float2(o[j][0] * inv0, o[j][1] * inv0);
        *(float2*)(ob1 + 8 * j) = make_float2(o[j][2] * inv1, o[j][3] * inv1);
    }
}

} // namespace

extern "C" void kernel_launch(void* const* d_in, const int* in_sizes, int n_in,
                              void* d_out, int out_size)
{
    const float* q  = (const float*)d_in[0];
    const float* k  = (const float*)d_in[1];
    const float* v  = (const float*)d_in[2];
    const float* pe = (const float*)d_in[3];
    float* out = (float*)d_out;

    prep_kernel<<<dim3((H * L * 64) / 256, 3), 256>>>(q, k, v, pe);

    cudaFuncSetAttribute(fa16_kernel,
                         cudaFuncAttributeMaxDynamicSharedMemorySize, SMEM_BYTES);
    fa16_kernel<<<dim3(L / BM, H), NTH, SMEM_BYTES>>>(out);
}